// round 1
// baseline (speedup 1.0000x reference)
#include <cuda_runtime.h>
#include <math.h>

// Problem constants: x (2,16,256,256) f32, conv_w (32,16,4,4), conv_b (32)
// out (2,32,256,256) f32. Ring of 40 offsets (radius 5), select 16 smallest
// sims (stable), per-rank conv weights.

#define B_      2
#define CCH     16
#define HH      256
#define WWIDTH  256
#define OUTC    32
#define NOFF    40
#define NSEL    16

#define TW 32
#define TH 8
#define SW 42              // TW + 2*5
#define SH 18              // TH + 2*5
#define CPLANE (SW*SH)     // 756
#define XS_FLOATS (CPLANE*CCH)   // 12096
#define WS_FLOATS (NSEL*CCH*OUTC) // 8192
#define CB_FLOATS 32
#define SMEM_BYTES ((XS_FLOATS + WS_FLOATS + CB_FLOATS)*4)

// Ring offset tables (compile-time): order must match _prf_offsets:
//  j 0..10 : dx=-5,        dy=j-5
//  j 11..19: dx=j-15,      dy=+5
//  j 20..30: dx=+5,        dy=j-25
//  j 31..39: dx=j-35,      dy=-5
__host__ __device__ constexpr int dxOf(int j){ return j<11 ? -5 : (j<20 ? j-15 : (j<31 ? 5 : j-35)); }
__host__ __device__ constexpr int dyOf(int j){ return j<11 ? j-5 : (j<20 ? 5 : (j<31 ? j-25 : -5)); }

__device__ __forceinline__ unsigned long long pack2(float a, float b){
    unsigned long long r;
    asm("mov.b64 %0, {%1,%2};" : "=l"(r) : "f"(a), "f"(b));
    return r;
}
__device__ __forceinline__ void fma2(unsigned long long &acc, unsigned long long a, unsigned long long b){
    asm("fma.rn.f32x2 %0, %1, %2, %0;" : "+l"(acc) : "l"(a), "l"(b));
}
__device__ __forceinline__ float2 unpack2(unsigned long long v){
    float2 f;
    asm("mov.b64 {%0,%1}, %2;" : "=f"(f.x), "=f"(f.y) : "l"(v));
    return f;
}

__global__ __launch_bounds__(TW*TH)
void pkc2d_kernel(const float* __restrict__ x,
                  const float* __restrict__ cw,
                  const float* __restrict__ cb,
                  float* __restrict__ out)
{
    extern __shared__ float sm[];
    float* xs  = sm;                       // [c][sy][sx], 16 x 18 x 42
    float* ws  = sm + XS_FLOATS;           // [r][c][o],  16 x 16 x 32
    float* cbs = ws + WS_FLOATS;           // [32]

    const int tx = threadIdx.x, ty = threadIdx.y;
    const int tid = ty*TW + tx;
    const int gx0 = blockIdx.x*TW, gy0 = blockIdx.y*TH;
    const int bz  = blockIdx.z;

    const float* xb = x + (size_t)bz * CCH * (HH*WWIDTH);

    // ---- cooperative loads: halo tile (zero-padded), weights (rank-major), bias ----
    for (int i = tid; i < XS_FLOATS; i += TW*TH) {
        int c   = i / CPLANE;
        int rem = i - c*CPLANE;
        int sy  = rem / SW;
        int sx  = rem - sy*SW;
        int gy  = gy0 + sy - 5;
        int gxp = gx0 + sx - 5;
        float v = 0.f;
        if ((unsigned)gy < (unsigned)HH && (unsigned)gxp < (unsigned)WWIDTH)
            v = xb[c*(HH*WWIDTH) + gy*WWIDTH + gxp];
        xs[i] = v;
    }
    // ws[((r*16)+c)*32 + o] = cw[o][c][r/4][r%4] = cw[o*256 + c*16 + r]
    for (int i = tid; i < WS_FLOATS; i += TW*TH) {
        int o  = i & 31;
        int rc = i >> 5;
        int r  = rc >> 4;
        int c  = rc & 15;
        ws[i] = cw[o*256 + c*16 + r];
    }
    if (tid < 32) cbs[tid] = cb[tid];
    __syncthreads();

    const int base = (ty+5)*SW + (tx+5);

    // center pixel channels
    float xc[CCH];
    #pragma unroll
    for (int c = 0; c < CCH; ++c) xc[c] = xs[c*CPLANE + base];

    // ---- sims for 40 ring offsets: mean over c, then sigmoid (fp32, mul-then-add
    //      in channel order to track the reference reduction) ----
    float sims[NOFF];
    #pragma unroll
    for (int j = 0; j < NOFF; ++j) {
        const int off = dxOf(j)*SW + dyOf(j);
        float s = 0.f;
        #pragma unroll
        for (int c = 0; c < CCH; ++c)
            s = __fadd_rn(s, __fmul_rn(xs[c*CPLANE + base + off], xc[c]));
        s *= 0.0625f;
        sims[j] = 1.0f / (1.0f + expf(-s));
    }

    // ---- accumulators (f32x2 over output-channel pairs), seeded with bias ----
    unsigned long long acc2[OUTC/2];
    #pragma unroll
    for (int q = 0; q < OUTC/2; ++q) acc2[q] = pack2(cbs[2*q], cbs[2*q+1]);

    // ---- 16-round stable min-selection fused with conv accumulation ----
    // strict '<' scan in ascending j => ties pick smallest index (stable argsort)
    unsigned mlo = 0u, mhi = 0u;   // taken mask
    #pragma unroll
    for (int r = 0; r < NSEL; ++r) {
        float best = 3.0e38f;
        int bestCombo = 0;
        #pragma unroll
        for (int j = 0; j < NOFF; ++j) {
            const int off   = dxOf(j)*SW + dyOf(j);
            const int combo = ((off + 512) << 6) | j;
            const unsigned taken = (j < 32) ? ((mlo >> j) & 1u)
                                            : ((mhi >> (j-32)) & 1u);
            if (!taken && sims[j] < best) { best = sims[j]; bestCombo = combo; }
        }
        const int bj = bestCombo & 63;
        if (bj < 32) mlo |= (1u << bj);
        else         mhi |= (1u << (bj - 32));
        const int addr = base + ((bestCombo >> 6) - 512);

        #pragma unroll
        for (int c = 0; c < CCH; ++c) {
            const float d = xc[c] - xs[c*CPLANE + addr];
            const unsigned long long d2 = pack2(d, d);
            const unsigned long long* wp =
                reinterpret_cast<const unsigned long long*>(ws + ((r*CCH + c) << 5));
            #pragma unroll
            for (int q = 0; q < OUTC/2; ++q) fma2(acc2[q], wp[q], d2);
        }
    }

    // ---- store ----
    const int px = gx0 + tx, py = gy0 + ty;
    float* ob = out + (size_t)bz*OUTC*(HH*WWIDTH) + py*WWIDTH + px;
    #pragma unroll
    for (int q = 0; q < OUTC/2; ++q) {
        float2 v = unpack2(acc2[q]);
        ob[(2*q  )*(HH*WWIDTH)] = v.x;
        ob[(2*q+1)*(HH*WWIDTH)] = v.y;
    }
}

extern "C" void kernel_launch(void* const* d_in, const int* in_sizes, int n_in,
                              void* d_out, int out_size)
{
    const float* x  = (const float*)d_in[0];
    const float* cw = (const float*)d_in[1];
    const float* cb = (const float*)d_in[2];
    float* out = (float*)d_out;

    cudaFuncSetAttribute(pkc2d_kernel,
                         cudaFuncAttributeMaxDynamicSharedMemorySize, SMEM_BYTES);

    dim3 block(TW, TH, 1);
    dim3 grid(WWIDTH/TW, HH/TH, B_);
    pkc2d_kernel<<<grid, block, SMEM_BYTES>>>(x, cw, cb, out);
}

// round 2
// speedup vs baseline: 1.4249x; 1.4249x over previous
#include <cuda_runtime.h>
#include <math.h>

// x (2,16,256,256) f32, conv_w (32,16,4,4), conv_b (32) -> out (2,32,256,256) f32.
// Ring of 40 offsets (radius 5), stable-select 16 smallest sigmoid-sims,
// rank-indexed 32x(16*16) mat-vec per pixel.

#define B_      2
#define CCH     16
#define HH      256
#define WWIDTH  256
#define HW      (HH*WWIDTH)
#define OUTC    32
#define NOFF    40
#define NSEL    16

#define TW 32
#define TH 8
#define NTHR (TW*TH)           // 256
#define SW 42                  // TW + 2*5
#define SH 18                  // TH + 2*5
#define CPLANE (SW*SH)         // 756
#define XS_FLOATS (CPLANE*CCH)        // 12096
#define WS_FLOATS (NSEL*CCH*OUTC)     // 8192
#define CB_FLOATS 32
#define SEL_WORDS (NSEL*NTHR)         // 4096
#define SMEM_BYTES ((XS_FLOATS + WS_FLOATS + CB_FLOATS + SEL_WORDS)*4)

// Ring offsets, order matching _prf_offsets:
//  j 0..10 : dx=-5,   dy=j-5
//  j 11..19: dx=j-15, dy=+5
//  j 20..30: dx=+5,   dy=j-25
//  j 31..39: dx=j-35, dy=-5
__host__ __device__ constexpr int dxOf(int j){ return j<11 ? -5 : (j<20 ? j-15 : (j<31 ? 5 : j-35)); }
__host__ __device__ constexpr int dyOf(int j){ return j<11 ? j-5 : (j<20 ? 5 : (j<31 ? j-25 : -5)); }
__host__ __device__ constexpr int offOf(int j){ return dxOf(j)*SW + dyOf(j); }

typedef unsigned long long u64;

__device__ __forceinline__ u64 pack2(float a, float b){
    u64 r;
    asm("mov.b64 %0, {%1,%2};" : "=l"(r) : "f"(a), "f"(b));
    return r;
}
__device__ __forceinline__ void fma2(u64 &acc, u64 a, u64 b){
    asm("fma.rn.f32x2 %0, %1, %2, %0;" : "+l"(acc) : "l"(a), "l"(b));
}
__device__ __forceinline__ float2 unpack2(u64 v){
    float2 f;
    asm("mov.b64 {%0,%1}, %2;" : "=f"(f.x), "=f"(f.y) : "l"(v));
    return f;
}

__global__ __launch_bounds__(NTHR, 2)
void pkc2d_kernel(const float* __restrict__ x,
                  const float* __restrict__ cw,
                  const float* __restrict__ cb,
                  float* __restrict__ out)
{
    extern __shared__ float sm[];
    float*    xs  = sm;                      // [c][sy][sx] 16 x 18 x 42
    float*    ws  = sm + XS_FLOATS;          // [r][c][o]   16 x 16 x 32
    float*    cbs = ws + WS_FLOATS;          // [32]
    unsigned* selp = (unsigned*)(cbs + CB_FLOATS); // [r][tid] 16 x 256

    const int tx = threadIdx.x, ty = threadIdx.y;
    const int tid = ty*TW + tx;
    const int gx0 = blockIdx.x*TW, gy0 = blockIdx.y*TH;
    const int bz  = blockIdx.z;

    const float* xb = x + (size_t)bz * CCH * HW;

    // ---- cooperative loads ----
    for (int i = tid; i < XS_FLOATS; i += NTHR) {
        int c   = i / CPLANE;
        int rem = i - c*CPLANE;
        int sy  = rem / SW;
        int sx  = rem - sy*SW;
        int gy  = gy0 + sy - 5;
        int gxp = gx0 + sx - 5;
        float v = 0.f;
        if ((unsigned)gy < (unsigned)HH && (unsigned)gxp < (unsigned)WWIDTH)
            v = xb[c*HW + gy*WWIDTH + gxp];
        xs[i] = v;
    }
    // ws[((r*16)+c)*32 + o] = cw[o*256 + c*16 + r]
    for (int i = tid; i < WS_FLOATS; i += NTHR) {
        int o  = i & 31;
        int rc = i >> 5;
        int r  = rc >> 4;
        int c  = rc & 15;
        ws[i] = cw[o*256 + c*16 + r];
    }
    if (tid < 32) cbs[tid] = cb[tid];
    __syncthreads();

    // ================= Phase 1: per-own-pixel selection =================
    {
        const int base = (ty+5)*SW + (tx+5);

        float xc[CCH];
        #pragma unroll
        for (int c = 0; c < CCH; ++c) xc[c] = xs[c*CPLANE + base];

        // sims (sequential channel-order add to track the reference reduction)
        float sims[NOFF];
        #pragma unroll
        for (int j = 0; j < NOFF; ++j) {
            const int off = offOf(j);
            float s = 0.f;
            #pragma unroll
            for (int c = 0; c < CCH; ++c)
                s = __fadd_rn(s, __fmul_rn(xs[c*CPLANE + base + off], xc[c]));
            s *= 0.0625f;
            sims[j] = 1.0f / (1.0f + expf(-s));
        }

        // rank[j] = #{jp: sims[jp]<sims[j]} + #{jp<j: sims[jp]==sims[j]}
        // (stable argsort rank; no loop-carried dependency)
        #pragma unroll
        for (int j = 0; j < NOFF; ++j) {
            int rk = 0;
            #pragma unroll
            for (int jp = 0; jp < NOFF; ++jp) {
                if (jp < j)       rk += (sims[jp] <= sims[j]) ? 1 : 0;
                else if (jp > j)  rk += (sims[jp] <  sims[j]) ? 1 : 0;
            }
            if (rk < NSEL)
                selp[rk*NTHR + tid] = (unsigned)(offOf(j) + 512);
        }
    }
    __syncthreads();

    // ================= Phase 2: pixel-pair / half-OUTC mat-vec =================
    // thread t: ph = t>>7 selects o in [16*ph, 16*ph+16); handles pixels
    // p0 = t&127 (rows 0..3) and p1 = p0+128 (rows 4..7) of the 32x8 tile.
    const int pp = tid & 127;
    const int ph = tid >> 7;
    const int px = pp & 31;
    const int py = pp >> 5;

    const int b0 = (py+5)*SW + (px+5);
    const int b1 = b0 + 4*SW;

    float xc0[CCH], xc1[CCH];
    #pragma unroll
    for (int c = 0; c < CCH; ++c) {
        xc0[c] = xs[c*CPLANE + b0];
        xc1[c] = xs[c*CPLANE + b1];
    }

    u64 accA[8], accB[8];
    #pragma unroll
    for (int q = 0; q < 8; ++q) {
        u64 seed = pack2(cbs[ph*16 + 2*q], cbs[ph*16 + 2*q + 1]);
        accA[q] = seed;
        accB[q] = seed;
    }

    #pragma unroll 1
    for (int r = 0; r < NSEL; ++r) {
        const int a0 = b0 + (int)selp[r*NTHR + pp]       - 512;
        const int a1 = b1 + (int)selp[r*NTHR + pp + 128] - 512;
        const u64* wp = reinterpret_cast<const u64*>(ws + (r << 9) + (ph << 4));
        #pragma unroll
        for (int c = 0; c < CCH; ++c) {
            const float d0 = xc0[c] - xs[c*CPLANE + a0];
            const float d1 = xc1[c] - xs[c*CPLANE + a1];
            const u64 d0p = pack2(d0, d0);
            const u64 d1p = pack2(d1, d1);
            const u64* w = wp + (c << 4);
            #pragma unroll
            for (int q = 0; q < 8; ++q) {
                fma2(accA[q], w[q], d0p);
                fma2(accB[q], w[q], d1p);
            }
        }
    }

    // ---- store: 16 o-channels x 2 pixels ----
    const int gx = gx0 + px;
    const int gy_a = gy0 + py;
    const int gy_b = gy_a + 4;
    float* ob = out + (size_t)bz*OUTC*HW + (size_t)(ph*16)*HW + gx;
    #pragma unroll
    for (int q = 0; q < 8; ++q) {
        float2 va = unpack2(accA[q]);
        float2 vb = unpack2(accB[q]);
        ob[(2*q  )*HW + gy_a*WWIDTH] = va.x;
        ob[(2*q+1)*HW + gy_a*WWIDTH] = va.y;
        ob[(2*q  )*HW + gy_b*WWIDTH] = vb.x;
        ob[(2*q+1)*HW + gy_b*WWIDTH] = vb.y;
    }
}

extern "C" void kernel_launch(void* const* d_in, const int* in_sizes, int n_in,
                              void* d_out, int out_size)
{
    const float* x  = (const float*)d_in[0];
    const float* cw = (const float*)d_in[1];
    const float* cb = (const float*)d_in[2];
    float* out = (float*)d_out;

    cudaFuncSetAttribute(pkc2d_kernel,
                         cudaFuncAttributeMaxDynamicSharedMemorySize, SMEM_BYTES);

    dim3 block(TW, TH, 1);
    dim3 grid(WWIDTH/TW, HH/TH, B_);
    pkc2d_kernel<<<grid, block, SMEM_BYTES>>>(x, cw, cb, out);
}